// round 1
// baseline (speedup 1.0000x reference)
#include <cuda_runtime.h>
#include <math.h>
#include <stdint.h>

// Problem constants
#define Bn   16384
#define OBSn 376
#define Hn   512
#define Mn   8
#define L1n  3
#define Tn   50
#define An   17
#define LOGS2PI 0.9189385332046727f

// ---------------- scratch (device globals; no allocation allowed) ----------------
__device__ float d_h1[(size_t)Bn * Hn];          // encoder hidden
__device__ float d_fs[(size_t)Bn * Hn];          // f_s
__device__ float d_rel[(size_t)Bn * Hn];         // relu(f_s * emb[idx])
__device__ float d_probsA[(size_t)Bn * L1n * 64];
__device__ float d_probsC[(size_t)Bn * L1n * 64];
__device__ float d_outs[(size_t)Bn * Mn * Hn];   // per-layer module outputs
__device__ float d_g0[(size_t)Bn * Mn * Hn];
__device__ float d_g1[(size_t)Bn * Mn * Hn];
__device__ float d_g2[(size_t)Bn * Mn * Hn];     // critic final g
__device__ float d_actorOut[(size_t)Bn * An];
__device__ float d_val[Bn];
__device__ float d_cst[32];                      // [0..16]=sum_m a_bf, [17]=log_prob, [18]=entropy, [19]=sum_m c_bf
__device__ int   d_is64;

// ---------------- task_idx dtype detector ----------------
// If buffer is int64 (LE) with values in [0,50): int32 words look like [v,0,v,0,...]
// -> all odd words zero, even words in range. If int32: odd words are task ids,
// P(all 512 odd words == 0) ~ (1/50)^512 == never.
__global__ void detect_kernel(const int* __restrict__ ti) {
    __shared__ int ok;
    if (threadIdx.x == 0) ok = 1;
    __syncthreads();
    for (int i = threadIdx.x; i < 1024; i += blockDim.x) {
        int v = ti[i];
        bool good = (i & 1) ? (v == 0) : (v >= 0 && v < Tn);
        if (!good) atomicAnd(&ok, 0);
    }
    __syncthreads();
    if (threadIdx.x == 0) d_is64 = ok;
}

// ---------------- generic fp32 GEMM: C = act(A[M,K] @ B[K,N] + bias) ----------------
// Tiles: BM=64, BN=64, BK=8, 256 threads, 4x4 per-thread micro tile.
// Requirements used here: M % 64 == 0 (always 16384), K % 8 == 0 (376/512/4096),
// lda even (float2 A loads). N guarded (17/64/512).
template<int ACT>  // 0=none, 1=relu, 2=tanh
__global__ __launch_bounds__(256) void gemm_kernel(
    const float* __restrict__ A, int lda,
    const float* __restrict__ Bm, int ldb,
    const float* __restrict__ bias,
    float* __restrict__ C, int ldc,
    int N, int K)
{
    __shared__ __align__(16) float As[8][64];   // [k][m]
    __shared__ __align__(16) float Bs[8][64];   // [k][n]
    const int t  = threadIdx.x;
    const int m0 = blockIdx.x * 64;
    const int n0 = blockIdx.y * 64;

    const int arow = t >> 2;          // 0..63
    const int akp  = (t & 3) * 2;     // 0,2,4,6
    const int bk0  = t >> 6;          // 0..3
    const int bc   = t & 63;          // 0..63
    const int tr   = t >> 4;          // 0..15
    const int tc   = t & 15;          // 0..15

    float acc[4][4];
#pragma unroll
    for (int i = 0; i < 4; i++)
#pragma unroll
        for (int j = 0; j < 4; j++) acc[i][j] = 0.f;

    const int nt = K >> 3;
    const float* Arow = A + (size_t)(m0 + arow) * lda;
    const int n_g = n0 + bc;
    const bool nok = (n_g < N);

    float2 ra; float rb0, rb1;
    // prefetch tile 0
    ra  = *(const float2*)(Arow + akp);
    rb0 = nok ? Bm[(size_t)bk0 * ldb + n_g] : 0.f;
    rb1 = nok ? Bm[(size_t)(bk0 + 4) * ldb + n_g] : 0.f;

    for (int kt = 0; kt < nt; ++kt) {
        As[akp][arow]     = ra.x;
        As[akp + 1][arow] = ra.y;
        Bs[bk0][bc]       = rb0;
        Bs[bk0 + 4][bc]   = rb1;
        __syncthreads();

        if (kt + 1 < nt) {
            const int kb = (kt + 1) << 3;
            ra = *(const float2*)(Arow + kb + akp);
            if (nok) {
                rb0 = Bm[(size_t)(kb + bk0) * ldb + n_g];
                rb1 = Bm[(size_t)(kb + bk0 + 4) * ldb + n_g];
            } else { rb0 = 0.f; rb1 = 0.f; }
        }

#pragma unroll
        for (int kk = 0; kk < 8; ++kk) {
            float4 av = *(const float4*)&As[kk][tr * 4];
            float4 bv = *(const float4*)&Bs[kk][tc * 4];
            float aa[4] = {av.x, av.y, av.z, av.w};
            float bb[4] = {bv.x, bv.y, bv.z, bv.w};
#pragma unroll
            for (int i = 0; i < 4; i++)
#pragma unroll
                for (int j = 0; j < 4; j++)
                    acc[i][j] = fmaf(aa[i], bb[j], acc[i][j]);
        }
        __syncthreads();
    }

#pragma unroll
    for (int j = 0; j < 4; j++) {
        const int n = n0 + tc * 4 + j;
        if (n < N) {
            const float bv = bias ? bias[n] : 0.f;
#pragma unroll
            for (int i = 0; i < 4; i++) {
                float v = acc[i][j] + bv;
                if (ACT == 1) v = fmaxf(v, 0.f);
                if (ACT == 2) v = tanhf(v);
                C[(size_t)(m0 + tr * 4 + i) * ldc + n] = v;
            }
        }
    }
}

// ---------------- rel = relu(f_s * task_emb[task_idx]) ----------------
__global__ void rel_kernel(const float* __restrict__ fs, const void* __restrict__ tidx,
                           const float* __restrict__ emb, float* __restrict__ rel) {
    const int gid = blockIdx.x * blockDim.x + threadIdx.x;  // Bn*128
    const int b  = gid >> 7;
    const int h4 = gid & 127;
    long long ti;
    if (d_is64) ti = ((const long long*)tidx)[b];
    else        ti = (long long)((const int*)tidx)[b];
    float4 f = *(const float4*)(fs + (size_t)b * Hn + h4 * 4);
    float4 e = *(const float4*)(emb + (size_t)ti * Hn + h4 * 4);
    float4 r;
    r.x = fmaxf(f.x * e.x, 0.f);
    r.y = fmaxf(f.y * e.y, 0.f);
    r.z = fmaxf(f.z * e.z, 0.f);
    r.w = fmaxf(f.w * e.w, 0.f);
    *(float4*)(rel + (size_t)b * Hn + h4 * 4) = r;
}

// ---------------- softmax over groups of 8 (in place), both nets ----------------
__global__ void softmax_kernel(float* __restrict__ pA, float* __restrict__ pC) {
    const int gid = blockIdx.x * blockDim.x + threadIdx.x;   // 2*Bn*24
    const int per = Bn * L1n * 8;
    float* p = (gid < per) ? (pA + (size_t)gid * 8) : (pC + (size_t)(gid - per) * 8);
    float v[8], mx = -1e30f;
#pragma unroll
    for (int j = 0; j < 8; j++) { v[j] = p[j]; mx = fmaxf(mx, v[j]); }
    float s = 0.f;
#pragma unroll
    for (int j = 0; j < 8; j++) { v[j] = __expf(v[j] - mx); s += v[j]; }
    const float inv = 1.f / s;
#pragma unroll
    for (int j = 0; j < 8; j++) p[j] = v[j] * inv;
}

// ---------------- mix: g'[b,i,h] = sum_j p[b,i,j] * outs[b,j,h] ----------------
// probs points at layer slice; row stride 192. 128 threads/block, block = one b.
__global__ void mix_kernel(const float* __restrict__ probs, const float* __restrict__ outs,
                           float* __restrict__ gout) {
    __shared__ float p[64];
    const int b = blockIdx.x;
    const int tid = threadIdx.x;
    if (tid < 64) p[tid] = probs[(size_t)b * (L1n * 64) + tid];
    __syncthreads();
    const float* ob = outs + (size_t)b * (Mn * Hn);
    float4 o[8];
#pragma unroll
    for (int j = 0; j < 8; j++)
        o[j] = *(const float4*)(ob + j * Hn + tid * 4);
#pragma unroll
    for (int i = 0; i < 8; i++) {
        float4 a = make_float4(0.f, 0.f, 0.f, 0.f);
#pragma unroll
        for (int j = 0; j < 8; j++) {
            const float w = p[i * 8 + j];
            a.x = fmaf(w, o[j].x, a.x);
            a.y = fmaf(w, o[j].y, a.y);
            a.z = fmaf(w, o[j].z, a.z);
            a.w = fmaf(w, o[j].w, a.w);
        }
        *(float4*)(gout + (size_t)b * (Mn * Hn) + i * Hn + tid * 4) = a;
    }
}

// ---------------- critic final: val[b] = sum_{m,h} g[b,m,h]*c_Wf[m,h] ----------------
__global__ void critic_kernel(const float* __restrict__ g, const float* __restrict__ wf,
                              float* __restrict__ val) {
    const int w    = (blockIdx.x * blockDim.x + threadIdx.x) >> 5;
    const int lane = threadIdx.x & 31;
    const float* gr = g + (size_t)w * (Mn * Hn);
    float s = 0.f;
    for (int i = lane; i < Mn * Hn; i += 32) s = fmaf(gr[i], wf[i], s);
#pragma unroll
    for (int off = 16; off > 0; off >>= 1) s += __shfl_xor_sync(0xFFFFFFFFu, s, off);
    if (lane == 0) val[w] = s;
}

// ---------------- constants: summed final biases + logstd reductions ----------------
__global__ void prep_kernel(const float* __restrict__ abf, const float* __restrict__ cbf,
                            const float* __restrict__ logstd) {
    const int t = threadIdx.x;
    if (t < An) {
        float s = 0.f;
        for (int m = 0; m < Mn; m++) s += abf[m * An + t];
        d_cst[t] = s;
    }
    if (t == 17) {
        float s = 0.f;
        for (int m = 0; m < Mn; m++) s += cbf[m];
        d_cst[19] = s;
    }
    if (t == 18) {
        float lp = 0.f, en = 0.f;
        for (int a = 0; a < An; a++) {
            lp += -logstd[a] - LOGS2PI;
            en += 0.5f + LOGS2PI + logstd[a];
        }
        d_cst[17] = lp;
        d_cst[18] = en;
    }
}

// ---------------- pack output: [mean(17), log_prob, entropy, value] ----------------
__global__ void pack_kernel(const float* __restrict__ actorOut, const float* __restrict__ val,
                            float* __restrict__ out) {
    const int gid = blockIdx.x * blockDim.x + threadIdx.x;   // Bn*20
    const int b = gid / 20, k = gid % 20;
    float v;
    if (k < An)        v = actorOut[(size_t)b * An + k];
    else if (k == 17)  v = d_cst[17];
    else if (k == 18)  v = d_cst[18];
    else               v = val[b] + d_cst[19];
    out[gid] = v;
}

// ---------------- host ----------------
extern "C" void kernel_launch(void* const* d_in, const int* in_sizes, int n_in,
                              void* d_out, int out_size) {
    const float* x      = (const float*)d_in[0];
    const void*  tidx   = d_in[1];
    const float* W1     = (const float*)d_in[2];
    const float* b1     = (const float*)d_in[3];
    const float* W2     = (const float*)d_in[4];
    const float* b2     = (const float*)d_in[5];
    const float* emb    = (const float*)d_in[6];
    const float* a_rW   = (const float*)d_in[7];
    const float* a_rb   = (const float*)d_in[8];
    const float* c_rW   = (const float*)d_in[9];
    const float* c_rb   = (const float*)d_in[10];
    const float* a_W    = (const float*)d_in[11];
    const float* a_b    = (const float*)d_in[12];
    const float* a_Wf   = (const float*)d_in[13];
    const float* a_bf   = (const float*)d_in[14];
    const float* c_W    = (const float*)d_in[15];
    const float* c_b    = (const float*)d_in[16];
    const float* c_Wf   = (const float*)d_in[17];
    const float* c_bf   = (const float*)d_in[18];
    const float* logstd = (const float*)d_in[19];
    float* out = (float*)d_out;

    float *h1, *fs, *rel, *pA, *pC, *outs, *g0, *g1, *g2, *actorOut, *val, *cst;
    cudaGetSymbolAddress((void**)&h1, d_h1);
    cudaGetSymbolAddress((void**)&fs, d_fs);
    cudaGetSymbolAddress((void**)&rel, d_rel);
    cudaGetSymbolAddress((void**)&pA, d_probsA);
    cudaGetSymbolAddress((void**)&pC, d_probsC);
    cudaGetSymbolAddress((void**)&outs, d_outs);
    cudaGetSymbolAddress((void**)&g0, d_g0);
    cudaGetSymbolAddress((void**)&g1, d_g1);
    cudaGetSymbolAddress((void**)&g2, d_g2);
    cudaGetSymbolAddress((void**)&actorOut, d_actorOut);
    cudaGetSymbolAddress((void**)&val, d_val);
    cudaGetSymbolAddress((void**)&cst, d_cst);

    const dim3 gFull(Bn / 64, Hn / 64);   // M=16384, N=512
    const dim3 gN64(Bn / 64, 1);          // N<=64

    detect_kernel<<<1, 256>>>((const int*)tidx);

    // Encoder: h1 = tanh(x @ W1 + b1); fs = tanh(h1 @ W2 + b2)
    gemm_kernel<2><<<gFull, 256>>>(x, OBSn, W1, Hn, b1, h1, Hn, Hn, OBSn);
    gemm_kernel<2><<<gFull, 256>>>(h1, Hn, W2, Hn, b2, fs, Hn, Hn, Hn);

    rel_kernel<<<(Bn * 128) / 256, 256>>>(fs, tidx, emb, rel);

    // Routing logits -> probs buffers, both nets, per layer
    for (int l = 0; l < L1n; l++) {
        gemm_kernel<0><<<gN64, 256>>>(rel, Hn, a_rW + (size_t)l * Hn * 64, 64,
                                      a_rb + (size_t)l * 64, pA + (size_t)l * 64,
                                      L1n * 64, 64, Hn);
        gemm_kernel<0><<<gN64, 256>>>(rel, Hn, c_rW + (size_t)l * Hn * 64, 64,
                                      c_rb + (size_t)l * 64, pC + (size_t)l * 64,
                                      L1n * 64, 64, Hn);
    }
    softmax_kernel<<<(2 * Bn * L1n * 8) / 256, 256>>>(pA, pC);

    // Base networks: critic uses pC -> g2 final; actor uses pA -> g0 final.
    // Critic chain: fs -> g0 -> g1 -> g2
    {
        const float* gprev = fs;
        float* gs[3] = {g0, g1, g2};
        for (int l = 0; l < L1n; l++) {
            for (int m = 0; m < Mn; m++) {
                const float* Aptr = (l == 0) ? fs : (gprev + (size_t)m * Hn);
                const int lda = (l == 0) ? Hn : (Mn * Hn);
                gemm_kernel<1><<<gFull, 256>>>(
                    Aptr, lda,
                    c_W + (size_t)(l * Mn + m) * Hn * Hn, Hn,
                    c_b + (size_t)(l * Mn + m) * Hn,
                    outs + (size_t)m * Hn, Mn * Hn, Hn, Hn);
            }
            mix_kernel<<<Bn, 128>>>(pC + (size_t)l * 64, outs, gs[l]);
            gprev = gs[l];
        }
    }
    // Actor chain: fs -> g0 -> g1 -> g0  (g2 holds critic final, untouched)
    {
        const float* gprev = fs;
        float* gs[3] = {g0, g1, g0};
        for (int l = 0; l < L1n; l++) {
            for (int m = 0; m < Mn; m++) {
                const float* Aptr = (l == 0) ? fs : (gprev + (size_t)m * Hn);
                const int lda = (l == 0) ? Hn : (Mn * Hn);
                gemm_kernel<1><<<gFull, 256>>>(
                    Aptr, lda,
                    a_W + (size_t)(l * Mn + m) * Hn * Hn, Hn,
                    a_b + (size_t)(l * Mn + m) * Hn,
                    outs + (size_t)m * Hn, Mn * Hn, Hn, Hn);
            }
            mix_kernel<<<Bn, 128>>>(pA + (size_t)l * 64, outs, gs[l]);
            gprev = gs[l];
        }
    }

    prep_kernel<<<1, 32>>>(a_bf, c_bf, logstd);

    // Actor final: [B, 8*512] @ [8*512, 17] + sum_m a_bf
    gemm_kernel<0><<<gN64, 256>>>(g0, Mn * Hn, a_Wf, An, cst, actorOut, An, An, Mn * Hn);
    // Critic final: dot per row
    critic_kernel<<<Bn / 8, 256>>>(g2, c_Wf, val);

    pack_kernel<<<(Bn * 20) / 256, 256>>>(actorOut, val, out);
}